// round 6
// baseline (speedup 1.0000x reference)
#include <cuda_runtime.h>
#include <cuda_bf16.h>
#include <mma.h>

using namespace nvcuda;

// Problem constants
#define NUM_PARTS     16
#define ROWS_PER_PART 257
#define M_REAL        4112        // 257 * 16 distinct table rows
#define VAE           768
#define OUTD          1024
#define BATCH         4096

// GEMM tiling: 128x256 block tile, 512 threads (16 warps of 64x32)
#define BM 128
#define BN 256
#define BK 64
#define M_TILES 33                 // ceil(4112/128)
#define M_PAD   (M_TILES * BM)     // 4224
#define GEMM_THREADS 512
#define STAGES 3

#define STRIDE_A (BK + 8)          // 72
#define STRIDE_B (BN + 8)          // 264
#define SMEM_A_BYTES (BM * STRIDE_A * 2)   // 18432
#define SMEM_B_BYTES (BK * STRIDE_B * 2)   // 33792
#define STAGE_BYTES  (SMEM_A_BYTES + SMEM_B_BYTES)   // 52224
#define EPI_BYTES    (BM * BN * 4)                   // 131072
#define PIPE_BYTES   (STAGES * STAGE_BYTES)          // 156672
#define GEMM_SMEM    (EPI_BYTES > PIPE_BYTES ? EPI_BYTES : PIPE_BYTES)

// Device-global scratch (allocation-free)
__device__ __nv_bfloat16 g_A [M_PAD * VAE];
__device__ __nv_bfloat16 g_W1[VAE * OUTD];
__device__ __nv_bfloat16 g_W2[OUTD * OUTD];
__device__ __nv_bfloat16 g_H [M_PAD * OUTD];
__device__ float         g_T [M_PAD * OUTD];

// ---------------------------------------------------------------------------
__device__ __forceinline__ void cp_async16(void* smem, const void* gmem) {
    unsigned s = (unsigned)__cvta_generic_to_shared(smem);
    asm volatile("cp.async.cg.shared.global [%0], [%1], 16;\n" :: "r"(s), "l"(gmem));
}
__device__ __forceinline__ void cp_commit() { asm volatile("cp.async.commit_group;\n"); }
__device__ __forceinline__ void cp_wait0()  { asm volatile("cp.async.wait_group 0;\n"); }
__device__ __forceinline__ void cp_wait1()  { asm volatile("cp.async.wait_group 1;\n"); }

__device__ __forceinline__ unsigned pack2(float a, float b) {
    __nv_bfloat162 t = __floats2bfloat162_rn(a, b);
    return *reinterpret_cast<unsigned*>(&t);
}

// ---------------------------------------------------------------------------
__global__ __launch_bounds__(256)
void convert_all(const float* __restrict__ emb,
                 const float* __restrict__ W1,
                 const float* __restrict__ W2)
{
    const int U1 = (M_PAD * VAE) / 4;
    const int U2 = (VAE * OUTD) / 4;
    const int U3 = (OUTD * OUTD) / 4;
    const int UT = U1 + U2 + U3;
    for (int u = blockIdx.x * blockDim.x + threadIdx.x; u < UT;
         u += gridDim.x * blockDim.x) {
        float4 v;
        __nv_bfloat16* dst;
        if (u < U1) {
            int e = u * 4;
            int row = e / VAE;
            if (row < M_REAL) v = *reinterpret_cast<const float4*>(emb + e);
            else              v = make_float4(0.f, 0.f, 0.f, 0.f);
            dst = g_A + e;
        } else if (u < U1 + U2) {
            int e = (u - U1) * 4;
            v = *reinterpret_cast<const float4*>(W1 + e);
            dst = g_W1 + e;
        } else {
            int e = (u - U1 - U2) * 4;
            v = *reinterpret_cast<const float4*>(W2 + e);
            dst = g_W2 + e;
        }
        uint2 p;
        p.x = pack2(v.x, v.y);
        p.y = pack2(v.z, v.w);
        *reinterpret_cast<uint2*>(dst) = p;
    }
}

// ---------------------------------------------------------------------------
// 3-stage pipelined bf16 GEMM: C[M_PAD, 1024] = A[M_PAD, K] @ B[K, 1024]
// One __syncthreads per k-iter; cp.async wait_group 1 steady-state.
// ---------------------------------------------------------------------------
template<int K, bool IS_L1>
__global__ __launch_bounds__(GEMM_THREADS)
void gemm_kern(const float* __restrict__ bias, const float* __restrict__ pe)
{
    extern __shared__ char smem[];
    const __nv_bfloat16* __restrict__ A  = IS_L1 ? g_A  : g_H;
    const __nv_bfloat16* __restrict__ Bw = IS_L1 ? g_W1 : g_W2;

    const int t  = threadIdx.x;
    const int m0 = blockIdx.y * BM;
    const int n0 = blockIdx.x * BN;
    const int w  = t >> 5;
    const int wm = (w >> 3) * 64;   // 2 warp-rows  (128/64)
    const int wn = (w & 7) * 32;    // 8 warp-cols  (256/32)

    wmma::fragment<wmma::accumulator, 16, 16, 16, float> acc[4][2];
    #pragma unroll
    for (int i = 0; i < 4; i++)
        #pragma unroll
        for (int j = 0; j < 2; j++)
            wmma::fill_fragment(acc[i][j], 0.0f);

    auto load_stage = [&](int s, int k0) {
        __nv_bfloat16* sA = (__nv_bfloat16*)(smem + s * STAGE_BYTES);
        __nv_bfloat16* sB = (__nv_bfloat16*)(smem + s * STAGE_BYTES + SMEM_A_BYTES);
        #pragma unroll
        for (int i = 0; i < 2; i++) {               // A: 1024 16B-chunks
            int ch = t + i * GEMM_THREADS;
            int r = ch >> 3, c8 = (ch & 7) * 8;
            cp_async16(sA + r * STRIDE_A + c8,
                       A + (size_t)(m0 + r) * K + k0 + c8);
        }
        #pragma unroll
        for (int i = 0; i < 4; i++) {               // B: 2048 16B-chunks
            int ch = t + i * GEMM_THREADS;
            int r = ch >> 5, c8 = (ch & 31) * 8;
            cp_async16(sB + r * STRIDE_B + c8,
                       Bw + (size_t)(k0 + r) * OUTD + n0 + c8);
        }
        cp_commit();
    };

    constexpr int NIT = K / BK;     // 12 or 16
    load_stage(0, 0);
    load_stage(1, BK);

    #pragma unroll 1
    for (int it = 0; it < NIT; it++) {
        if (it + 1 < NIT) cp_wait1(); else cp_wait0();   // stage `it` is resident
        __syncthreads();
        if (it + 2 < NIT) load_stage((it + 2) % STAGES, (it + 2) * BK);

        const int s = it % STAGES;
        const __nv_bfloat16* sA = (const __nv_bfloat16*)(smem + s * STAGE_BYTES);
        const __nv_bfloat16* sB = (const __nv_bfloat16*)(smem + s * STAGE_BYTES + SMEM_A_BYTES);

        #pragma unroll
        for (int kk = 0; kk < BK; kk += 16) {
            wmma::fragment<wmma::matrix_a, 16, 16, 16, __nv_bfloat16, wmma::row_major> af[4];
            wmma::fragment<wmma::matrix_b, 16, 16, 16, __nv_bfloat16, wmma::row_major> bfr[2];
            #pragma unroll
            for (int i = 0; i < 4; i++)
                wmma::load_matrix_sync(af[i], sA + (wm + 16 * i) * STRIDE_A + kk, STRIDE_A);
            #pragma unroll
            for (int j = 0; j < 2; j++)
                wmma::load_matrix_sync(bfr[j], sB + kk * STRIDE_B + wn + 16 * j, STRIDE_B);
            #pragma unroll
            for (int i = 0; i < 4; i++)
                #pragma unroll
                for (int j = 0; j < 2; j++)
                    wmma::mma_sync(acc[i][j], af[i], bfr[j], acc[i][j]);
        }
    }
    __syncthreads();   // all warps done with smem before epilogue reuse

    // ---- epilogue ----
    float* sC = (float*)smem;   // 131072 <= GEMM_SMEM
    #pragma unroll
    for (int i = 0; i < 4; i++)
        #pragma unroll
        for (int j = 0; j < 2; j++)
            wmma::store_matrix_sync(sC + (wm + 16 * i) * BN + wn + 16 * j,
                                    acc[i][j], BN, wmma::mem_row_major);
    __syncthreads();

    const int c4 = t & 63;             // 64 float4 columns
    const int gc = n0 + c4 * 4;
    const float4 bias4 = *reinterpret_cast<const float4*>(bias + gc);

    #pragma unroll
    for (int i = 0; i < 16; i++) {
        int r  = (t >> 6) + i * 8;     // 0..127
        int gr = m0 + r;
        float4 v = *reinterpret_cast<const float4*>(sC + r * BN + c4 * 4);
        v.x += bias4.x; v.y += bias4.y; v.z += bias4.z; v.w += bias4.w;
        if (IS_L1) {
            v.x = fmaxf(v.x, 0.f); v.y = fmaxf(v.y, 0.f);
            v.z = fmaxf(v.z, 0.f); v.w = fmaxf(v.w, 0.f);
            uint2 p;
            p.x = pack2(v.x, v.y);
            p.y = pack2(v.z, v.w);
            *reinterpret_cast<uint2*>(g_H + (size_t)gr * OUTD + gc) = p;
        } else {
            int p = gr / ROWS_PER_PART; if (p > NUM_PARTS - 1) p = NUM_PARTS - 1;
            const float4 pe4 = *reinterpret_cast<const float4*>(pe + (size_t)p * OUTD + gc);
            v.x += pe4.x; v.y += pe4.y; v.z += pe4.z; v.w += pe4.w;
            *reinterpret_cast<float4*>(g_T + (size_t)gr * OUTD + gc) = v;
        }
    }
}

// ---------------------------------------------------------------------------
// Expand: one warp per (b,p) row. 1 hash load, 8 independent row loads
// (MLP=8, same 4KB table row), 8 streaming 16B stores (4KB contiguous/warp).
// ---------------------------------------------------------------------------
#define EXP_BLOCKS  1184
#define EXP_THREADS 256
#define EXP_WARPS   (EXP_BLOCKS * (EXP_THREADS / 32))   // 9472

__global__ __launch_bounds__(EXP_THREADS)
void expand_kernel(const int* __restrict__ hashes, float* __restrict__ out)
{
    const int warp = blockIdx.x * (EXP_THREADS / 32) + (threadIdx.x >> 5);
    const int lane = threadIdx.x & 31;
    float4* __restrict__ o4 = reinterpret_cast<float4*>(out);

    #pragma unroll 1
    for (int bp = warp; bp < BATCH * NUM_PARTS; bp += EXP_WARPS) {
        const int p = bp & (NUM_PARTS - 1);
        const int h = __ldg(hashes + bp);
        const float4* __restrict__ src = reinterpret_cast<const float4*>(
            g_T + (size_t)(h + p * ROWS_PER_PART) * OUTD) + lane;
        float4* __restrict__ dst = o4 + (size_t)bp * (OUTD / 4) + lane;

        float4 v[8];
        #pragma unroll
        for (int j = 0; j < 8; j++) v[j] = __ldg(src + 32 * j);
        #pragma unroll
        for (int j = 0; j < 8; j++) __stcs(dst + 32 * j, v[j]);
    }
}

// ---------------------------------------------------------------------------
extern "C" void kernel_launch(void* const* d_in, const int* in_sizes, int n_in,
                              void* d_out, int out_size)
{
    const int*   hashes = nullptr;
    const float* emb = nullptr; const float* W1 = nullptr; const float* W2 = nullptr;
    const float* pe  = nullptr; const float* b1 = nullptr; const float* b2 = nullptr;
    for (int i = 0; i < n_in; i++) {
        switch (in_sizes[i]) {
            case BATCH * NUM_PARTS: hashes = (const int*)d_in[i];   break;
            case M_REAL * VAE:      emb    = (const float*)d_in[i]; break;
            case VAE * OUTD:        W1     = (const float*)d_in[i]; break;
            case OUTD * OUTD:       W2     = (const float*)d_in[i]; break;
            case NUM_PARTS * OUTD:  pe     = (const float*)d_in[i]; break;
            case OUTD:
                if (!b1) b1 = (const float*)d_in[i]; else b2 = (const float*)d_in[i];
                break;
            default: break;
        }
    }
    float* out = (float*)d_out;

    cudaFuncSetAttribute(gemm_kern<VAE,  true >,
                         cudaFuncAttributeMaxDynamicSharedMemorySize, GEMM_SMEM);
    cudaFuncSetAttribute(gemm_kern<OUTD, false>,
                         cudaFuncAttributeMaxDynamicSharedMemorySize, GEMM_SMEM);

    convert_all<<<2048, 256>>>(emb, W1, W2);
    gemm_kern<VAE,  true ><<<dim3(OUTD / BN, M_TILES), GEMM_THREADS, GEMM_SMEM>>>(b1, nullptr);
    gemm_kern<OUTD, false><<<dim3(OUTD / BN, M_TILES), GEMM_THREADS, GEMM_SMEM>>>(b2, pe);
    expand_kernel<<<EXP_BLOCKS, EXP_THREADS>>>(hashes, out);
    (void)out_size;
}